// round 2
// baseline (speedup 1.0000x reference)
#include <cuda_runtime.h>

// Problem constants
#define S_LEN 32768
#define HDIM  1024
#define H3    3072        // attn_w row stride (3*H)
#define BM    128         // s-rows per CTA
#define BN    128         // i-cols per tile
#define BK    16          // k-chunk
#define NTHR  256
#define GRID2 (S_LEN / BM)   // 256 CTAs for the main kernel

// Scratch (no allocations allowed -> __device__ globals)
__device__ float g_c[HDIM];       // c[i] = hidden . attn_w[i,0:2H] + b[i]
__device__ float g_part[GRID2];   // per-CTA partial sums of exp(logit)
__device__ float g_inv;           // 1 / total sum

// ---------------------------------------------------------------------------
// Kernel 1: c[i] = sum_{j<2H} hidden[j]*attn_w[i*3H+j] + attn_b[i]
// One warp per i. 1024 warps = 128 blocks * 8 warps.
// ---------------------------------------------------------------------------
__global__ void precompute_c_kernel(const float* __restrict__ hidden,
                                    const float* __restrict__ attn_w,
                                    const float* __restrict__ attn_b) {
    int warp = (blockIdx.x * blockDim.x + threadIdx.x) >> 5;
    int lane = threadIdx.x & 31;
    if (warp >= HDIM) return;
    const float* wrow = attn_w + (size_t)warp * H3;
    float s = 0.f;
    #pragma unroll 8
    for (int j = lane; j < 2 * HDIM; j += 32)
        s += hidden[j] * wrow[j];
    #pragma unroll
    for (int off = 16; off; off >>= 1)
        s += __shfl_down_sync(0xffffffffu, s, off);
    if (lane == 0) g_c[warp] = s + attn_b[warp];
}

// ---------------------------------------------------------------------------
// Kernel 2: fused  logit[s] = sum_i v[i]*tanh(c[i] + enc[s,:].W2[i,:])
//           out[s] = exp(logit[s]);  g_part[blk] = sum of exps in this block.
// 128x128 output tile per i-chunk, 16x16 thread grid, 8x8 values per thread.
// Inner product uses packed fma.rn.f32x2 (2 s-rows per instruction).
// ---------------------------------------------------------------------------
__global__ __launch_bounds__(NTHR, 2)
void attn_main_kernel(const float* __restrict__ enc,
                      const float* __restrict__ attn_w,
                      const float* __restrict__ v_w,
                      float* __restrict__ out) {
    __shared__ float As[BK][BM];     // As[k][s]  (k-major for broadcast reads)
    __shared__ float Bs[BK][BN];     // Bs[k][i]
    __shared__ float esum[16];

    const int tid = threadIdx.x;
    const int tx  = tid & 15;        // i-group: cols tx*8 .. tx*8+7
    const int ty  = tid >> 4;        // s-group: rows ty*8 .. ty*8+7
    const int s0  = blockIdx.x * BM;

    float part[8];
    #pragma unroll
    for (int r = 0; r < 8; r++) part[r] = 0.f;

    for (int it = 0; it < HDIM / BN; it++) {
        // acc[p][c]: packed pair of s-rows (2p, 2p+1) x i-col c
        unsigned long long acc[4][8];
        #pragma unroll
        for (int p = 0; p < 4; p++)
            #pragma unroll
            for (int c = 0; c < 8; c++) acc[p][c] = 0ull;

        for (int kt = 0; kt < HDIM; kt += BK) {
            // cooperative tile load: 128 rows x 16 k, as float4 (512 per tile)
            #pragma unroll
            for (int l = 0; l < 2; l++) {
                int idx = tid + l * NTHR;        // 0..511
                int row = idx >> 2;              // 0..127
                int kq  = idx & 3;               // float4 slot in k
                float4 va = *(const float4*)(enc + (size_t)(s0 + row) * HDIM + kt + kq * 4);
                As[kq * 4 + 0][row] = va.x;
                As[kq * 4 + 1][row] = va.y;
                As[kq * 4 + 2][row] = va.z;
                As[kq * 4 + 3][row] = va.w;
                float4 vb = *(const float4*)(attn_w + (size_t)(it * BN + row) * H3
                                             + 2 * HDIM + kt + kq * 4);
                Bs[kq * 4 + 0][row] = vb.x;
                Bs[kq * 4 + 1][row] = vb.y;
                Bs[kq * 4 + 2][row] = vb.z;
                Bs[kq * 4 + 3][row] = vb.w;
            }
            __syncthreads();

            #pragma unroll
            for (int k = 0; k < BK; k++) {
                // a: 4 packed pairs of consecutive s-rows (8-byte aligned)
                unsigned long long a2[4];
                const unsigned long long* arow =
                    reinterpret_cast<const unsigned long long*>(&As[k][ty * 8]);
                #pragma unroll
                for (int p = 0; p < 4; p++) a2[p] = arow[p];

                // b: 8 scalars via two vector loads, then splat-pack
                float4 blo = *(const float4*)&Bs[k][tx * 8];
                float4 bhi = *(const float4*)&Bs[k][tx * 8 + 4];
                float bv[8] = {blo.x, blo.y, blo.z, blo.w,
                               bhi.x, bhi.y, bhi.z, bhi.w};
                #pragma unroll
                for (int c = 0; c < 8; c++) {
                    unsigned long long b2;
                    unsigned int bu = __float_as_uint(bv[c]);
                    asm("mov.b64 %0, {%1, %1};" : "=l"(b2) : "r"(bu));
                    #pragma unroll
                    for (int p = 0; p < 4; p++) {
                        asm("fma.rn.f32x2 %0, %1, %2, %0;"
                            : "+l"(acc[p][c]) : "l"(a2[p]), "l"(b2));
                    }
                }
            }
            __syncthreads();
        }

        // epilogue for this i-tile: tanh + v-dot accumulation
        #pragma unroll
        for (int c = 0; c < 8; c++) {
            int i = it * BN + tx * 8 + c;
            float ci = g_c[i];
            float vi = __ldg(v_w + i);
            #pragma unroll
            for (int p = 0; p < 4; p++) {
                float2 e2 = *reinterpret_cast<float2*>(&acc[p][c]);
                part[2 * p + 0] += vi * tanhf(e2.x + ci);
                part[2 * p + 1] += vi * tanhf(e2.y + ci);
            }
        }
    }

    // reduce over the 16 tx threads sharing each s-row (segments of 16 lanes)
    #pragma unroll
    for (int r = 0; r < 8; r++) {
        float v = part[r];
        v += __shfl_down_sync(0xffffffffu, v, 8, 16);
        v += __shfl_down_sync(0xffffffffu, v, 4, 16);
        v += __shfl_down_sync(0xffffffffu, v, 2, 16);
        v += __shfl_down_sync(0xffffffffu, v, 1, 16);
        part[r] = v;
    }
    if (tx == 0) {
        float lsum = 0.f;
        #pragma unroll
        for (int r = 0; r < 8; r++) {
            // |logit| <= sum|v_i| ~ 25  ->  exp is safe without max-shift
            float ex = expf(part[r]);
            out[s0 + ty * 8 + r] = ex;
            lsum += ex;
        }
        esum[ty] = lsum;
    }
    __syncthreads();
    if (tid == 0) {
        float t = 0.f;
        #pragma unroll
        for (int y = 0; y < 16; y++) t += esum[y];
        g_part[blockIdx.x] = t;
    }
}

// ---------------------------------------------------------------------------
// Kernel 3: deterministic reduction of 256 block partials -> g_inv
// ---------------------------------------------------------------------------
__global__ void reduce_total_kernel() {
    __shared__ float sm[GRID2];
    int t = threadIdx.x;
    sm[t] = g_part[t];
    __syncthreads();
    #pragma unroll
    for (int o = GRID2 / 2; o > 0; o >>= 1) {
        if (t < o) sm[t] += sm[t + o];
        __syncthreads();
    }
    if (t == 0) g_inv = 1.f / sm[0];
}

// ---------------------------------------------------------------------------
// Kernel 4: normalize in place
// ---------------------------------------------------------------------------
__global__ void normalize_kernel(float* __restrict__ out) {
    int i = blockIdx.x * blockDim.x + threadIdx.x;
    if (i < S_LEN) out[i] *= g_inv;
}

// ---------------------------------------------------------------------------
// Inputs (metadata order): hidden[2048], encoder_output[S*H],
//                          attn_w[H*3H], attn_b[H], v_w[H]
// Output: float[S]
// ---------------------------------------------------------------------------
extern "C" void kernel_launch(void* const* d_in, const int* in_sizes, int n_in,
                              void* d_out, int out_size) {
    const float* hidden = (const float*)d_in[0];
    const float* enc    = (const float*)d_in[1];
    const float* attn_w = (const float*)d_in[2];
    const float* attn_b = (const float*)d_in[3];
    const float* v_w    = (const float*)d_in[4];
    float* out = (float*)d_out;

    precompute_c_kernel<<<128, 256>>>(hidden, attn_w, attn_b);
    attn_main_kernel<<<GRID2, NTHR>>>(enc, attn_w, v_w, out);
    reduce_total_kernel<<<1, GRID2>>>();
    normalize_kernel<<<S_LEN / 256, 256>>>(out);
}

// round 4
// speedup vs baseline: 3.3946x; 3.3946x over previous
#include <cuda_runtime.h>
#include <cstdint>

#define S_LEN 32768
#define HDIM  1024
#define H3    3072
#define BM    128
#define BN    256                 // i-cols per pass
#define NPASS 4
#define KCH   32                  // k floats per chunk
#define NCHUNKS (NPASS * (HDIM / KCH))   // 128
#define GRID_MAIN (S_LEN / BM)    // 256

// SMEM (bytes). Padded strides: 36 floats/row -> conflict-free frag loads.
#define A_STG  18432              // 128 rows * 36 * 4
#define B_STG  36864              // 256 rows * 36 * 4
#define SM_A   0                  // 2 stages
#define SM_B   (2 * A_STG)        // 36864, 2 stages
#define SM_C   (SM_B + 2 * B_STG) // 110592
#define SM_V   (SM_C + 4096)
#define SM_RED (SM_V + 4096)      // 2*128 floats
#define SM_SR  (SM_RED + 1024)    // 4 floats
#define SMEM_TOTAL (SM_SR + 16)

__device__ float g_c[HDIM];
__device__ float g_part[GRID_MAIN];
__device__ float g_inv;

// ---------------- helpers ----------------
__device__ __forceinline__ unsigned smem_u32(const void* p) {
    return (unsigned)__cvta_generic_to_shared(p);
}
__device__ __forceinline__ uint32_t f2tf(float x) {
    uint32_t r;
    asm("cvt.rna.tf32.f32 %0, %1;" : "=r"(r) : "f"(x));
    return r;
}
__device__ __forceinline__ float fast_tanh(float x) {
    // tanh(x) = 1 - 2/(1 + 2^(2*log2(e)*x));  saturates correctly at +-inf
    float e, r;
    asm("ex2.approx.f32 %0, %1;" : "=f"(e) : "f"(x * 2.885390082f));
    asm("rcp.approx.f32 %0, %1;" : "=f"(r) : "f"(e + 1.0f));
    return fmaf(-2.0f, r, 1.0f);
}
__device__ __forceinline__ void mma8(float* d, const uint32_t* a,
                                     uint32_t b0, uint32_t b1) {
    asm volatile(
        "mma.sync.aligned.m16n8k8.row.col.f32.tf32.tf32.f32 "
        "{%0,%1,%2,%3}, {%4,%5,%6,%7}, {%8,%9}, {%0,%1,%2,%3};"
        : "+f"(d[0]), "+f"(d[1]), "+f"(d[2]), "+f"(d[3])
        : "r"(a[0]), "r"(a[1]), "r"(a[2]), "r"(a[3]), "r"(b0), "r"(b1));
}

// cp.async one chunk: A 128x32f, B 256x32f into padded-stride buffers
__device__ __forceinline__ void load_chunk(unsigned sb, int stage, int gc,
                                           int s0, int tid,
                                           const float* __restrict__ enc,
                                           const float* __restrict__ attn_w) {
    const int kt = (gc & 31) * KCH;
    const int i0 = (gc >> 5) * BN;
    const unsigned ab = sb + SM_A + stage * A_STG;
    const unsigned bb = sb + SM_B + stage * B_STG;
    #pragma unroll
    for (int j = 0; j < 4; j++) {              // A: 1024 x 16B
        int idx = tid + j * 256;
        int row = idx >> 3, q = idx & 7;
        unsigned dst = ab + (unsigned)(row * 144 + q * 16);
        const float* src = enc + (size_t)(s0 + row) * HDIM + kt + q * 4;
        asm volatile("cp.async.cg.shared.global [%0], [%1], 16;"
                     :: "r"(dst), "l"(src) : "memory");
    }
    #pragma unroll
    for (int j = 0; j < 8; j++) {              // B: 2048 x 16B
        int idx = tid + j * 256;
        int row = idx >> 3, q = idx & 7;
        unsigned dst = bb + (unsigned)(row * 144 + q * 16);
        const float* src = attn_w + (size_t)(i0 + row) * H3 + 2 * HDIM + kt + q * 4;
        asm volatile("cp.async.cg.shared.global [%0], [%1], 16;"
                     :: "r"(dst), "l"(src) : "memory");
    }
    asm volatile("cp.async.commit_group;" ::: "memory");
}

// ---------------------------------------------------------------------------
// Kernel 1: c[i] = hidden . attn_w[i, 0:2H] + attn_b[i]
// ---------------------------------------------------------------------------
__global__ void precompute_c_kernel(const float* __restrict__ hidden,
                                    const float* __restrict__ attn_w,
                                    const float* __restrict__ attn_b) {
    int warp = (blockIdx.x * blockDim.x + threadIdx.x) >> 5;
    int lane = threadIdx.x & 31;
    if (warp >= HDIM) return;
    const float* wrow = attn_w + (size_t)warp * H3;
    float s = 0.f;
    #pragma unroll 8
    for (int j = lane; j < 2 * HDIM; j += 32)
        s += hidden[j] * wrow[j];
    #pragma unroll
    for (int off = 16; off; off >>= 1)
        s += __shfl_down_sync(0xffffffffu, s, off);
    if (lane == 0) g_c[warp] = s + attn_b[warp];
}

// ---------------------------------------------------------------------------
// Kernel 2: tf32 mma.sync GEMM + fused tanh / v-dot / exp epilogue.
//   8 warps = 4(M) x 2(N).  Warp tile 32x128.  128 accums/thread.
// ---------------------------------------------------------------------------
__global__ __launch_bounds__(256, 1)
void attn_main_kernel(const float* __restrict__ enc,
                      const float* __restrict__ attn_w,
                      const float* __restrict__ v_w,
                      float* __restrict__ out) {
    extern __shared__ char smem[];
    const unsigned sb = smem_u32(smem);
    const int tid  = threadIdx.x;
    const int wid  = tid >> 5;
    const int lane = tid & 31;
    const int g    = lane >> 2;      // group id (rows / n-cols)
    const int c    = lane & 3;       // thread-in-group (k / out-cols)
    const int m0   = (wid & 3) * 32; // warp M offset
    const int n0   = (wid >> 2) * 128;
    const int s0   = blockIdx.x * BM;

    float* sc   = (float*)(smem + SM_C);
    float* sv   = (float*)(smem + SM_V);
    float* red  = (float*)(smem + SM_RED);
    float* sr   = (float*)(smem + SM_SR);

    for (int i = tid; i < HDIM; i += 256) { sc[i] = g_c[i]; sv[i] = v_w[i]; }

    // prologue: chunks 0, 1
    load_chunk(sb, 0, 0, s0, tid, enc, attn_w);
    load_chunk(sb, 1, 1, s0, tid, enc, attn_w);

    float acc[2][16][4];
    float part[4] = {0.f, 0.f, 0.f, 0.f};

    for (int gc = 0; gc < NCHUNKS; gc++) {
        const int b = gc & 1;
        if (gc == NCHUNKS - 1)
            asm volatile("cp.async.wait_group 0;" ::: "memory");
        else
            asm volatile("cp.async.wait_group 1;" ::: "memory");
        __syncthreads();

        if ((gc & 31) == 0) {
            #pragma unroll
            for (int mt = 0; mt < 2; mt++)
                #pragma unroll
                for (int nt = 0; nt < 16; nt++)
                    #pragma unroll
                    for (int q = 0; q < 4; q++) acc[mt][nt][q] = 0.f;
        }

        const float* Ab = (const float*)(smem + SM_A + b * A_STG);
        const float* Bb = (const float*)(smem + SM_B + b * B_STG);

        #pragma unroll
        for (int ks = 0; ks < 4; ks++) {
            const int k0 = ks * 8;
            uint32_t afrag[2][4];
            #pragma unroll
            for (int mt = 0; mt < 2; mt++) {
                int r = m0 + mt * 16 + g;
                afrag[mt][0] = f2tf(Ab[r * 36 + k0 + c]);
                afrag[mt][1] = f2tf(Ab[(r + 8) * 36 + k0 + c]);
                afrag[mt][2] = f2tf(Ab[r * 36 + k0 + c + 4]);
                afrag[mt][3] = f2tf(Ab[(r + 8) * 36 + k0 + c + 4]);
            }
            #pragma unroll
            for (int nt = 0; nt < 16; nt++) {
                int col = n0 + nt * 8 + g;
                uint32_t b0 = f2tf(Bb[col * 36 + k0 + c]);
                uint32_t b1 = f2tf(Bb[col * 36 + k0 + c + 4]);
                mma8(acc[0][nt], afrag[0], b0, b1);
                mma8(acc[1][nt], afrag[1], b0, b1);
            }
        }
        __syncthreads();                 // all reads done before refill

        if (gc + 2 < NCHUNKS)
            load_chunk(sb, b, gc + 2, s0, tid, enc, attn_w);

        // per-pass fused epilogue: tanh + v-dot into register partials
        if ((gc & 31) == 31) {
            const int pass = gc >> 5;
            #pragma unroll
            for (int mt = 0; mt < 2; mt++) {
                #pragma unroll
                for (int nt = 0; nt < 16; nt++) {
                    int i = pass * BN + n0 + nt * 8 + c * 2;
                    float v0 = sv[i],  c0 = sc[i];
                    float v1 = sv[i+1], c1 = sc[i+1];
                    part[mt*2+0] = fmaf(v0, fast_tanh(acc[mt][nt][0] + c0),
                                   fmaf(v1, fast_tanh(acc[mt][nt][1] + c1),
                                        part[mt*2+0]));
                    part[mt*2+1] = fmaf(v0, fast_tanh(acc[mt][nt][2] + c0),
                                   fmaf(v1, fast_tanh(acc[mt][nt][3] + c1),
                                        part[mt*2+1]));
                }
            }
        }
    }

    // reduce the 4 quad lanes (same rows, different out-col pairs)
    #pragma unroll
    for (int q = 0; q < 4; q++) {
        part[q] += __shfl_xor_sync(0xffffffffu, part[q], 1);
        part[q] += __shfl_xor_sync(0xffffffffu, part[q], 2);
    }
    // each warp covers rows m0..m0+31; two n-warps contribute per row
    if (c == 0) {
        const int nw = wid >> 2;
        #pragma unroll
        for (int q = 0; q < 4; q++) {
            int row = m0 + (q >> 1) * 16 + (q & 1) * 8 + g;
            red[nw * 128 + row] = part[q];
        }
    }
    __syncthreads();

    // logits -> exp -> output + deterministic block partial
    float ex = 0.f;
    if (tid < BM) {
        float logit = red[tid] + red[128 + tid];   // |logit| <= ~26
        ex = expf(logit);
        out[s0 + tid] = ex;
    }
    #pragma unroll
    for (int off = 16; off; off >>= 1)
        ex += __shfl_down_sync(0xffffffffu, ex, off);
    if (lane == 0 && wid < 4) sr[wid] = ex;
    __syncthreads();
    if (tid == 0)
        g_part[blockIdx.x] = sr[0] + sr[1] + sr[2] + sr[3];
}

// ---------------------------------------------------------------------------
// Kernel 3: deterministic reduction -> g_inv
// ---------------------------------------------------------------------------
__global__ void reduce_total_kernel() {
    __shared__ float sm[GRID_MAIN];
    int t = threadIdx.x;
    sm[t] = g_part[t];
    __syncthreads();
    #pragma unroll
    for (int o = GRID_MAIN / 2; o > 0; o >>= 1) {
        if (t < o) sm[t] += sm[t + o];
        __syncthreads();
    }
    if (t == 0) g_inv = 1.f / sm[0];
}

// ---------------------------------------------------------------------------
// Kernel 4: normalize
// ---------------------------------------------------------------------------
__global__ void normalize_kernel(float* __restrict__ out) {
    int i = blockIdx.x * blockDim.x + threadIdx.x;
    if (i < S_LEN) out[i] *= g_inv;
}

// ---------------------------------------------------------------------------
extern "C" void kernel_launch(void* const* d_in, const int* in_sizes, int n_in,
                              void* d_out, int out_size) {
    const float* hidden = (const float*)d_in[0];
    const float* enc    = (const float*)d_in[1];
    const float* attn_w = (const float*)d_in[2];
    const float* attn_b = (const float*)d_in[3];
    const float* v_w    = (const float*)d_in[4];
    float* out = (float*)d_out;

    cudaFuncSetAttribute(attn_main_kernel,
                         cudaFuncAttributeMaxDynamicSharedMemorySize, SMEM_TOTAL);

    precompute_c_kernel<<<128, 256>>>(hidden, attn_w, attn_b);
    attn_main_kernel<<<GRID_MAIN, 256, SMEM_TOTAL>>>(enc, attn_w, v_w, out);
    reduce_total_kernel<<<1, GRID_MAIN>>>();
    normalize_kernel<<<S_LEN / 256, 256>>>(out);
}

// round 5
// speedup vs baseline: 3.7837x; 1.1146x over previous
#include <cuda_runtime.h>
#include <cstdint>

#define S_LEN 32768
#define HDIM  1024
#define H3    3072
#define BM    128
#define BN    256                 // i-cols per pass
#define NPASS 4
#define KCH   32                  // k floats per chunk
#define NCHUNKS (NPASS * (HDIM / KCH))   // 128
#define GRID_MAIN (S_LEN / BM)    // 256
#define NSTAGE 3

// SMEM (bytes). Row stride 36 floats -> conflict-free fragment loads.
#define A_STG  18432              // 128 * 36 * 4
#define B_STG  36864              // 256 * 36 * 4
#define SM_A   0
#define SM_B   (NSTAGE * A_STG)               // 55296
#define SM_C   (SM_B + NSTAGE * B_STG)        // 165888
#define SM_V   (SM_C + 4096)                  // 169984
#define SM_RED (SM_V + 4096)                  // 174080 (512 floats)
#define SM_SR  (SM_RED + 2048)                // 176128
#define SMEM_TOTAL (SM_SR + 16)               // 176144

// RTZ-shrink compensation: tf32 truncation of both operands biases the
// GEMM output by ~ -2^-10 multiplicatively; undo it in the epilogue.
#define TF32_COMP 1.000977f

__device__ float g_c[HDIM];
__device__ float g_part[GRID_MAIN];
__device__ float g_inv;

// ---------------- helpers ----------------
__device__ __forceinline__ unsigned smem_u32(const void* p) {
    return (unsigned)__cvta_generic_to_shared(p);
}
__device__ __forceinline__ float fast_tanh(float x) {
    // tanh(x) = 1 - 2/(1 + 2^(2*log2(e)*x)); saturates correctly at +-inf
    float e, r;
    asm("ex2.approx.f32 %0, %1;" : "=f"(e) : "f"(x * 2.885390082f));
    asm("rcp.approx.f32 %0, %1;" : "=f"(r) : "f"(e + 1.0f));
    return fmaf(-2.0f, r, 1.0f);
}
__device__ __forceinline__ void mma8(float* d, const uint32_t* a,
                                     uint32_t b0, uint32_t b1) {
    asm volatile(
        "mma.sync.aligned.m16n8k8.row.col.f32.tf32.tf32.f32 "
        "{%0,%1,%2,%3}, {%4,%5,%6,%7}, {%8,%9}, {%0,%1,%2,%3};"
        : "+f"(d[0]), "+f"(d[1]), "+f"(d[2]), "+f"(d[3])
        : "r"(a[0]), "r"(a[1]), "r"(a[2]), "r"(a[3]), "r"(b0), "r"(b1));
}

// cp.async one chunk: A 128x32f, B 256x32f into padded-stride buffers
__device__ __forceinline__ void load_chunk(unsigned sb, int stage, int gc,
                                           int s0, int tid,
                                           const float* __restrict__ enc,
                                           const float* __restrict__ attn_w) {
    const int kt = (gc & 31) * KCH;
    const int i0 = (gc >> 5) * BN;
    const unsigned ab = sb + SM_A + stage * A_STG;
    const unsigned bb = sb + SM_B + stage * B_STG;
    #pragma unroll
    for (int j = 0; j < 4; j++) {              // A: 1024 x 16B
        int idx = tid + j * 256;
        int row = idx >> 3, q = idx & 7;
        unsigned dst = ab + (unsigned)(row * 144 + q * 16);
        const float* src = enc + (size_t)(s0 + row) * HDIM + kt + q * 4;
        asm volatile("cp.async.cg.shared.global [%0], [%1], 16;"
                     :: "r"(dst), "l"(src) : "memory");
    }
    #pragma unroll
    for (int j = 0; j < 8; j++) {              // B: 2048 x 16B
        int idx = tid + j * 256;
        int row = idx >> 3, q = idx & 7;
        unsigned dst = bb + (unsigned)(row * 144 + q * 16);
        const float* src = attn_w + (size_t)(i0 + row) * H3 + 2 * HDIM + kt + q * 4;
        asm volatile("cp.async.cg.shared.global [%0], [%1], 16;"
                     :: "r"(dst), "l"(src) : "memory");
    }
    asm volatile("cp.async.commit_group;" ::: "memory");
}

// ---------------------------------------------------------------------------
// Kernel 1: c[i] = hidden . attn_w[i, 0:2H] + attn_b[i]
// ---------------------------------------------------------------------------
__global__ void precompute_c_kernel(const float* __restrict__ hidden,
                                    const float* __restrict__ attn_w,
                                    const float* __restrict__ attn_b) {
    int warp = (blockIdx.x * blockDim.x + threadIdx.x) >> 5;
    int lane = threadIdx.x & 31;
    if (warp >= HDIM) return;
    const float* wrow = attn_w + (size_t)warp * H3;
    float s = 0.f;
    #pragma unroll 8
    for (int j = lane; j < 2 * HDIM; j += 32)
        s += hidden[j] * wrow[j];
    #pragma unroll
    for (int off = 16; off; off >>= 1)
        s += __shfl_down_sync(0xffffffffu, s, off);
    if (lane == 0) g_c[warp] = s + attn_b[warp];
}

// ---------------------------------------------------------------------------
// Kernel 2: tf32 mma.sync GEMM + fused tanh / v-dot / exp epilogue.
//   8 warps = 2(M) x 4(N).  Warp tile 64x64.  mt=4, nt=8.  No cvt (HW RTZ).
// ---------------------------------------------------------------------------
__global__ __launch_bounds__(256, 1)
void attn_main_kernel(const float* __restrict__ enc,
                      const float* __restrict__ attn_w,
                      const float* __restrict__ v_w,
                      float* __restrict__ out) {
    extern __shared__ char smem[];
    const unsigned sb = smem_u32(smem);
    const int tid  = threadIdx.x;
    const int wid  = tid >> 5;
    const int lane = tid & 31;
    const int g    = lane >> 2;        // 0..7
    const int c    = lane & 3;         // 0..3
    const int m0   = (wid >> 2) * 64;  // 2 M-warps
    const int n0   = (wid & 3) * 64;   // 4 N-warps
    const int s0   = blockIdx.x * BM;

    float* sc  = (float*)(smem + SM_C);
    float* sv  = (float*)(smem + SM_V);
    float* red = (float*)(smem + SM_RED);
    float* sr  = (float*)(smem + SM_SR);

    for (int i = tid; i < HDIM; i += 256) { sc[i] = g_c[i]; sv[i] = v_w[i]; }

    // prologue: chunks 0, 1 into stages 0, 1
    load_chunk(sb, 0, 0, s0, tid, enc, attn_w);
    load_chunk(sb, 1, 1, s0, tid, enc, attn_w);

    float acc[4][8][4];
    float part[8];
    #pragma unroll
    for (int r = 0; r < 8; r++) part[r] = 0.f;

    for (int gc = 0; gc < NCHUNKS; gc++) {
        const int stage = gc % NSTAGE;
        if (gc < NCHUNKS - 1)
            asm volatile("cp.async.wait_group 1;" ::: "memory");
        else
            asm volatile("cp.async.wait_group 0;" ::: "memory");
        __syncthreads();

        // refill the stage freed two iterations ago (safe: all warps synced)
        if (gc + 2 < NCHUNKS)
            load_chunk(sb, (gc + 2) % NSTAGE, gc + 2, s0, tid, enc, attn_w);

        if ((gc & 31) == 0) {
            #pragma unroll
            for (int mt = 0; mt < 4; mt++)
                #pragma unroll
                for (int nt = 0; nt < 8; nt++)
                    #pragma unroll
                    for (int q = 0; q < 4; q++) acc[mt][nt][q] = 0.f;
        }

        const uint32_t* Ab = (const uint32_t*)(smem + SM_A + stage * A_STG);
        const uint32_t* Bb = (const uint32_t*)(smem + SM_B + stage * B_STG);

        #pragma unroll
        for (int ks = 0; ks < 4; ks++) {
            const int k0 = ks * 8;
            uint32_t af[4][4];
            #pragma unroll
            for (int mt = 0; mt < 4; mt++) {
                int r = m0 + mt * 16 + g;
                af[mt][0] = Ab[r * 36 + k0 + c];
                af[mt][1] = Ab[(r + 8) * 36 + k0 + c];
                af[mt][2] = Ab[r * 36 + k0 + c + 4];
                af[mt][3] = Ab[(r + 8) * 36 + k0 + c + 4];
            }
            #pragma unroll
            for (int nt = 0; nt < 8; nt++) {
                int col = n0 + nt * 8 + g;
                uint32_t b0 = Bb[col * 36 + k0 + c];
                uint32_t b1 = Bb[col * 36 + k0 + c + 4];
                #pragma unroll
                for (int mt = 0; mt < 4; mt++)
                    mma8(acc[mt][nt], af[mt], b0, b1);
            }
        }

        // per-pass fused epilogue: tanh + v-dot into register partials
        if ((gc & 31) == 31) {
            const int pass = gc >> 5;
            #pragma unroll
            for (int mt = 0; mt < 4; mt++) {
                #pragma unroll
                for (int nt = 0; nt < 8; nt++) {
                    int i = pass * BN + n0 + nt * 8 + c * 2;
                    float v0 = sv[i],     c0 = sc[i];
                    float v1 = sv[i + 1], c1 = sc[i + 1];
                    part[mt*2+0] = fmaf(v0, fast_tanh(fmaf(acc[mt][nt][0], TF32_COMP, c0)),
                                   fmaf(v1, fast_tanh(fmaf(acc[mt][nt][1], TF32_COMP, c1)),
                                        part[mt*2+0]));
                    part[mt*2+1] = fmaf(v0, fast_tanh(fmaf(acc[mt][nt][2], TF32_COMP, c0)),
                                   fmaf(v1, fast_tanh(fmaf(acc[mt][nt][3], TF32_COMP, c1)),
                                        part[mt*2+1]));
                }
            }
        }
    }

    // reduce the 4 quad lanes (same rows, different col pairs)
    #pragma unroll
    for (int r = 0; r < 8; r++) {
        part[r] += __shfl_xor_sync(0xffffffffu, part[r], 1);
        part[r] += __shfl_xor_sync(0xffffffffu, part[r], 2);
    }
    // 4 N-warps contribute per row; each writes its own slice of red[]
    if (c == 0) {
        const int nw = wid & 3;
        #pragma unroll
        for (int mt = 0; mt < 4; mt++) {
            #pragma unroll
            for (int h = 0; h < 2; h++) {
                int row = m0 + mt * 16 + h * 8 + g;
                red[nw * 128 + row] = part[mt * 2 + h];
            }
        }
    }
    __syncthreads();

    // logits -> exp -> output + deterministic block partial
    float ex = 0.f;
    if (tid < BM) {
        float logit = red[tid] + red[128 + tid] + red[256 + tid] + red[384 + tid];
        ex = expf(logit);                         // |logit| <= ~26, unshifted safe
        out[s0 + tid] = ex;
    }
    #pragma unroll
    for (int off = 16; off; off >>= 1)
        ex += __shfl_down_sync(0xffffffffu, ex, off);
    if (lane == 0 && wid < 4) sr[wid] = ex;
    __syncthreads();
    if (tid == 0)
        g_part[blockIdx.x] = sr[0] + sr[1] + sr[2] + sr[3];
}

// ---------------------------------------------------------------------------
// Kernel 3: deterministic reduction -> g_inv
// ---------------------------------------------------------------------------
__global__ void reduce_total_kernel() {
    __shared__ float sm[GRID_MAIN];
    int t = threadIdx.x;
    sm[t] = g_part[t];
    __syncthreads();
    #pragma unroll
    for (int o = GRID_MAIN / 2; o > 0; o >>= 1) {
        if (t < o) sm[t] += sm[t + o];
        __syncthreads();
    }
    if (t == 0) g_inv = 1.f / sm[0];
}

// ---------------------------------------------------------------------------
// Kernel 4: normalize
// ---------------------------------------------------------------------------
__global__ void normalize_kernel(float* __restrict__ out) {
    int i = blockIdx.x * blockDim.x + threadIdx.x;
    if (i < S_LEN) out[i] *= g_inv;
}

// ---------------------------------------------------------------------------
extern "C" void kernel_launch(void* const* d_in, const int* in_sizes, int n_in,
                              void* d_out, int out_size) {
    const float* hidden = (const float*)d_in[0];
    const float* enc    = (const float*)d_in[1];
    const float* attn_w = (const float*)d_in[2];
    const float* attn_b = (const float*)d_in[3];
    const float* v_w    = (const float*)d_in[4];
    float* out = (float*)d_out;

    cudaFuncSetAttribute(attn_main_kernel,
                         cudaFuncAttributeMaxDynamicSharedMemorySize, SMEM_TOTAL);

    precompute_c_kernel<<<128, 256>>>(hidden, attn_w, attn_b);
    attn_main_kernel<<<GRID_MAIN, 256, SMEM_TOTAL>>>(enc, attn_w, v_w, out);
    reduce_total_kernel<<<1, GRID_MAIN>>>();
    normalize_kernel<<<S_LEN / 256, 256>>>(out);
}

// round 6
// speedup vs baseline: 4.0637x; 1.0740x over previous
#include <cuda_runtime.h>
#include <cstdint>

#define S_LEN 32768
#define HDIM  1024
#define H3    3072
#define BM    128
#define BN    256                 // i-cols per pass
#define NPASS 4
#define KCH   32                  // k floats per chunk
#define NCHUNKS (NPASS * (HDIM / KCH))   // 128
#define GRID_MAIN (S_LEN / BM)    // 256
#define NSTAGE 3

// SMEM (bytes). Row stride 36 floats (144 B) -> conflict-free ldmatrix.
#define A_STG  18432              // 128 * 144
#define B_STG  36864              // 256 * 144
#define SM_A   0
#define SM_B   (NSTAGE * A_STG)               // 55296
#define SM_C   (SM_B + NSTAGE * B_STG)        // 165888
#define SM_V   (SM_C + 4096)                  // 169984
#define SM_RED (SM_V + 4096)                  // 174080 (512 floats)
#define SM_SR  (SM_RED + 2048)                // 176128
#define SMEM_TOTAL (SM_SR + 16)               // 176144

// RTZ-shrink compensation for feeding raw f32 into tf32 MMA (HW truncates).
#define TF32_COMP 1.000977f

__device__ float g_c[HDIM];
__device__ float g_part[GRID_MAIN];
__device__ float g_inv;

// ---------------- helpers ----------------
__device__ __forceinline__ unsigned smem_u32(const void* p) {
    return (unsigned)__cvta_generic_to_shared(p);
}
__device__ __forceinline__ float fast_tanh(float x) {
    float e, r;
    asm("ex2.approx.f32 %0, %1;" : "=f"(e) : "f"(x * 2.885390082f));
    asm("rcp.approx.f32 %0, %1;" : "=f"(r) : "f"(e + 1.0f));
    return fmaf(-2.0f, r, 1.0f);
}
__device__ __forceinline__ void mma8(float* d, const uint32_t* a,
                                     uint32_t b0, uint32_t b1) {
    asm volatile(
        "mma.sync.aligned.m16n8k8.row.col.f32.tf32.tf32.f32 "
        "{%0,%1,%2,%3}, {%4,%5,%6,%7}, {%8,%9}, {%0,%1,%2,%3};"
        : "+f"(d[0]), "+f"(d[1]), "+f"(d[2]), "+f"(d[3])
        : "r"(a[0]), "r"(a[1]), "r"(a[2]), "r"(a[3]), "r"(b0), "r"(b1));
}
// ldmatrix x4: four 8x8 b16 tiles == four 8x4 f32 tiles (tf32 fragments)
__device__ __forceinline__ void ldsm4(uint32_t* d, unsigned addr) {
    asm volatile(
        "ldmatrix.sync.aligned.m8n8.x4.shared.b16 {%0,%1,%2,%3}, [%4];"
        : "=r"(d[0]), "=r"(d[1]), "=r"(d[2]), "=r"(d[3]) : "r"(addr));
}

// cp.async one chunk: A 128x32f, B 256x32f into padded-stride buffers
__device__ __forceinline__ void load_chunk(unsigned sb, int stage, int gc,
                                           int s0, int tid,
                                           const float* __restrict__ enc,
                                           const float* __restrict__ attn_w) {
    const int kt = (gc & 31) * KCH;
    const int i0 = (gc >> 5) * BN;
    const unsigned ab = sb + SM_A + stage * A_STG;
    const unsigned bb = sb + SM_B + stage * B_STG;
    #pragma unroll
    for (int j = 0; j < 4; j++) {              // A: 1024 x 16B
        int idx = tid + j * 256;
        int row = idx >> 3, q = idx & 7;
        unsigned dst = ab + (unsigned)(row * 144 + q * 16);
        const float* src = enc + (size_t)(s0 + row) * HDIM + kt + q * 4;
        asm volatile("cp.async.cg.shared.global [%0], [%1], 16;"
                     :: "r"(dst), "l"(src) : "memory");
    }
    #pragma unroll
    for (int j = 0; j < 8; j++) {              // B: 2048 x 16B
        int idx = tid + j * 256;
        int row = idx >> 3, q = idx & 7;
        unsigned dst = bb + (unsigned)(row * 144 + q * 16);
        const float* src = attn_w + (size_t)(i0 + row) * H3 + 2 * HDIM + kt + q * 4;
        asm volatile("cp.async.cg.shared.global [%0], [%1], 16;"
                     :: "r"(dst), "l"(src) : "memory");
    }
    asm volatile("cp.async.commit_group;" ::: "memory");
}

// ---------------------------------------------------------------------------
// Kernel 1: c[i] = hidden . attn_w[i, 0:2H] + attn_b[i]
// ---------------------------------------------------------------------------
__global__ void precompute_c_kernel(const float* __restrict__ hidden,
                                    const float* __restrict__ attn_w,
                                    const float* __restrict__ attn_b) {
    int warp = (blockIdx.x * blockDim.x + threadIdx.x) >> 5;
    int lane = threadIdx.x & 31;
    if (warp >= HDIM) return;
    const float* wrow = attn_w + (size_t)warp * H3;
    float s = 0.f;
    #pragma unroll 8
    for (int j = lane; j < 2 * HDIM; j += 32)
        s += hidden[j] * wrow[j];
    #pragma unroll
    for (int off = 16; off; off >>= 1)
        s += __shfl_down_sync(0xffffffffu, s, off);
    if (lane == 0) g_c[warp] = s + attn_b[warp];
}

// ---------------------------------------------------------------------------
// Kernel 2: tf32 mma.sync GEMM, fragments via ldmatrix.x4,
//           fused tanh / v-dot / exp epilogue.
//   8 warps = 2(M) x 4(N).  Warp tile 64x64.  mt=4, nt=8.
// ---------------------------------------------------------------------------
__global__ __launch_bounds__(256, 1)
void attn_main_kernel(const float* __restrict__ enc,
                      const float* __restrict__ attn_w,
                      const float* __restrict__ v_w,
                      float* __restrict__ out) {
    extern __shared__ char smem[];
    const unsigned sb = smem_u32(smem);
    const int tid  = threadIdx.x;
    const int wid  = tid >> 5;
    const int lane = tid & 31;
    const int g    = lane >> 2;        // 0..7
    const int c    = lane & 3;         // 0..3
    const int m0   = (wid >> 2) * 64;  // 2 M-warps
    const int n0   = (wid & 3) * 64;   // 4 N-warps
    const int s0   = blockIdx.x * BM;

    float* sc  = (float*)(smem + SM_C);
    float* sv  = (float*)(smem + SM_V);
    float* red = (float*)(smem + SM_RED);
    float* sr  = (float*)(smem + SM_SR);

    for (int i = tid; i < HDIM; i += 256) { sc[i] = g_c[i]; sv[i] = v_w[i]; }

    // ldmatrix lane-fixed offsets (bytes), stride 144 B/row
    // A x4 tile (per mt, ks): mats {rows+0,cols k0}, {rows+8,k0}, {+0,k0+4}, {+8,k0+4}
    const unsigned aLane =
        (unsigned)((m0 + ((lane >> 3) & 1) * 8 + (lane & 7)) * 144
                   + (lane >> 4) * 16);
    // B x4 tile (per p, ks): mats {nt=2p,k0}, {nt=2p,k0+4}, {nt=2p+1,k0}, {nt=2p+1,k0+4}
    const unsigned bLane =
        (unsigned)((n0 + (lane >> 4) * 8 + (lane & 7)) * 144
                   + ((lane >> 3) & 1) * 16);

    // prologue: chunks 0, 1 into stages 0, 1
    load_chunk(sb, 0, 0, s0, tid, enc, attn_w);
    load_chunk(sb, 1, 1, s0, tid, enc, attn_w);

    float acc[4][8][4];
    float part[8];
    #pragma unroll
    for (int r = 0; r < 8; r++) part[r] = 0.f;

    for (int gc = 0; gc < NCHUNKS; gc++) {
        const int stage = gc % NSTAGE;
        if (gc < NCHUNKS - 1)
            asm volatile("cp.async.wait_group 1;" ::: "memory");
        else
            asm volatile("cp.async.wait_group 0;" ::: "memory");
        __syncthreads();

        if (gc + 2 < NCHUNKS)
            load_chunk(sb, (gc + 2) % NSTAGE, gc + 2, s0, tid, enc, attn_w);

        if ((gc & 31) == 0) {
            #pragma unroll
            for (int mt = 0; mt < 4; mt++)
                #pragma unroll
                for (int nt = 0; nt < 8; nt++)
                    #pragma unroll
                    for (int q = 0; q < 4; q++) acc[mt][nt][q] = 0.f;
        }

        const unsigned aB = sb + SM_A + stage * A_STG + aLane;
        const unsigned bB = sb + SM_B + stage * B_STG + bLane;

        #pragma unroll
        for (int ks = 0; ks < 4; ks++) {
            uint32_t af[4][4], bf[4][4];
            #pragma unroll
            for (int mt = 0; mt < 4; mt++)
                ldsm4(af[mt], aB + mt * (16 * 144) + ks * 32);
            #pragma unroll
            for (int p = 0; p < 4; p++)
                ldsm4(bf[p], bB + p * (16 * 144) + ks * 32);
            #pragma unroll
            for (int p = 0; p < 4; p++) {
                #pragma unroll
                for (int mt = 0; mt < 4; mt++) {
                    mma8(acc[mt][2 * p + 0], af[mt], bf[p][0], bf[p][1]);
                    mma8(acc[mt][2 * p + 1], af[mt], bf[p][2], bf[p][3]);
                }
            }
        }

        // per-pass fused epilogue: tanh + v-dot into register partials
        if ((gc & 31) == 31) {
            const int pass = gc >> 5;
            #pragma unroll
            for (int mt = 0; mt < 4; mt++) {
                #pragma unroll
                for (int nt = 0; nt < 8; nt++) {
                    int i = pass * BN + n0 + nt * 8 + c * 2;
                    float v0 = sv[i],     c0 = sc[i];
                    float v1 = sv[i + 1], c1 = sc[i + 1];
                    part[mt*2+0] = fmaf(v0, fast_tanh(fmaf(acc[mt][nt][0], TF32_COMP, c0)),
                                   fmaf(v1, fast_tanh(fmaf(acc[mt][nt][1], TF32_COMP, c1)),
                                        part[mt*2+0]));
                    part[mt*2+1] = fmaf(v0, fast_tanh(fmaf(acc[mt][nt][2], TF32_COMP, c0)),
                                   fmaf(v1, fast_tanh(fmaf(acc[mt][nt][3], TF32_COMP, c1)),
                                        part[mt*2+1]));
                }
            }
        }
    }

    // reduce the 4 quad lanes (same rows, different col pairs)
    #pragma unroll
    for (int r = 0; r < 8; r++) {
        part[r] += __shfl_xor_sync(0xffffffffu, part[r], 1);
        part[r] += __shfl_xor_sync(0xffffffffu, part[r], 2);
    }
    if (c == 0) {
        const int nw = wid & 3;
        #pragma unroll
        for (int mt = 0; mt < 4; mt++) {
            #pragma unroll
            for (int h = 0; h < 2; h++) {
                int row = m0 + mt * 16 + h * 8 + g;
                red[nw * 128 + row] = part[mt * 2 + h];
            }
        }
    }
    __syncthreads();

    float ex = 0.f;
    if (tid < BM) {
        float logit = red[tid] + red[128 + tid] + red[256 + tid] + red[384 + tid];
        ex = expf(logit);                         // |logit| <= ~26
        out[s0 + tid] = ex;
    }
    #pragma unroll
    for (int off = 16; off; off >>= 1)
        ex += __shfl_down_sync(0xffffffffu, ex, off);
    if (lane == 0 && wid < 4) sr[wid] = ex;
    __syncthreads();
    if (tid == 0)
        g_part[blockIdx.x] = sr[0] + sr[1] + sr[2] + sr[3];
}

// ---------------------------------------------------------------------------
// Kernel 3: deterministic reduction -> g_inv
// ---------------------------------------------------------------------------
__global__ void reduce_total_kernel() {
    __shared__ float sm[GRID_MAIN];
    int t = threadIdx.x;
    sm[t] = g_part[t];
    __syncthreads();
    #pragma unroll
    for (int o = GRID_MAIN / 2; o > 0; o >>= 1) {
        if (t < o) sm[t] += sm[t + o];
        __syncthreads();
    }
    if (t == 0) g_inv = 1.f / sm[0];
}

// ---------------------------------------------------------------------------
// Kernel 4: normalize
// ---------------------------------------------------------------------------
__global__ void normalize_kernel(float* __restrict__ out) {
    int i = blockIdx.x * blockDim.x + threadIdx.x;
    if (i < S_LEN) out[i] *= g_inv;
}

// ---------------------------------------------------------------------------
extern "C" void kernel_launch(void* const* d_in, const int* in_sizes, int n_in,
                              void* d_out, int out_size) {
    const float* hidden = (const float*)d_in[0];
    const float* enc    = (const float*)d_in[1];
    const float* attn_w = (const float*)d_in[2];
    const float* attn_b = (const float*)d_in[3];
    const float* v_w    = (const float*)d_in[4];
    float* out = (float*)d_out;

    cudaFuncSetAttribute(attn_main_kernel,
                         cudaFuncAttributeMaxDynamicSharedMemorySize, SMEM_TOTAL);

    precompute_c_kernel<<<128, 256>>>(hidden, attn_w, attn_b);
    attn_main_kernel<<<GRID_MAIN, 256, SMEM_TOTAL>>>(enc, attn_w, v_w, out);
    reduce_total_kernel<<<1, GRID_MAIN>>>();
    normalize_kernel<<<S_LEN / 256, 256>>>(out);
}

// round 7
// speedup vs baseline: 5.9415x; 1.4621x over previous
#include <cuda_runtime.h>
#include <cuda_bf16.h>
#include <cstdint>

#define S_LEN 32768
#define HDIM  1024
#define H3    3072
#define BM    128
#define BN    128                  // i-cols per pass
#define NPASS 8
#define KCH   32                   // k elements per chunk (64 B bf16 row)
#define NCHUNKS (NPASS * (HDIM / KCH))   // 256
#define GRID_MAIN (S_LEN / BM)     // 256
#define NSTAGE 3

// SMEM (bytes). Row stride 80 B (32 bf16 + 16 B pad) -> conflict-free ldmatrix.
#define A_STG  10240               // 128 * 80
#define B_STG  10240               // 128 * 80
#define SM_A   0
#define SM_B   (NSTAGE * A_STG)              // 30720
#define SM_C   (SM_B + NSTAGE * B_STG)       // 61440
#define SM_V   (SM_C + 4096)                 // 65536
#define SM_RED (SM_V + 4096)                 // 69632 (256 floats)
#define SM_SR  (SM_RED + 1024)               // 70656
#define SMEM_TOTAL (SM_SR + 16)              // 70672  (x2 CTA/SM = 141 KB)

__device__ float g_c[HDIM];
__device__ float g_part[GRID_MAIN];
__device__ float g_inv;
__device__ __align__(16) __nv_bfloat16 g_encb[(size_t)S_LEN * HDIM]; // 64 MB
__device__ __align__(16) __nv_bfloat16 g_wb[HDIM * HDIM];            // 2 MB

// ---------------- helpers ----------------
__device__ __forceinline__ unsigned smem_u32(const void* p) {
    return (unsigned)__cvta_generic_to_shared(p);
}
__device__ __forceinline__ float fast_tanh(float x) {
    float e, r;
    asm("ex2.approx.f32 %0, %1;" : "=f"(e) : "f"(x * 2.885390082f));
    asm("rcp.approx.f32 %0, %1;" : "=f"(r) : "f"(e + 1.0f));
    return fmaf(-2.0f, r, 1.0f);
}
__device__ __forceinline__ void mma16(float* d, const uint32_t* a,
                                      uint32_t b0, uint32_t b1) {
    asm volatile(
        "mma.sync.aligned.m16n8k16.row.col.f32.bf16.bf16.f32 "
        "{%0,%1,%2,%3}, {%4,%5,%6,%7}, {%8,%9}, {%0,%1,%2,%3};"
        : "+f"(d[0]), "+f"(d[1]), "+f"(d[2]), "+f"(d[3])
        : "r"(a[0]), "r"(a[1]), "r"(a[2]), "r"(a[3]), "r"(b0), "r"(b1));
}
__device__ __forceinline__ void ldsm4(uint32_t* d, unsigned addr) {
    asm volatile(
        "ldmatrix.sync.aligned.m8n8.x4.shared.b16 {%0,%1,%2,%3}, [%4];"
        : "=r"(d[0]), "=r"(d[1]), "=r"(d[2]), "=r"(d[3]) : "r"(addr));
}

// cp.async one chunk: A 128x32 bf16, B 128x32 bf16 (80 B row stride)
__device__ __forceinline__ void load_chunk(unsigned sb, int stage, int gc,
                                           int s0, int tid) {
    const int kt = (gc & 31) * KCH;
    const int i0 = (gc >> 5) * BN;
    const unsigned ab = sb + SM_A + stage * A_STG;
    const unsigned bb = sb + SM_B + stage * B_STG;
    #pragma unroll
    for (int j = 0; j < 2; j++) {              // A: 512 x 16B
        int idx = tid + j * 256;
        int row = idx >> 2, q = idx & 3;
        unsigned dst = ab + (unsigned)(row * 80 + q * 16);
        const __nv_bfloat16* src = g_encb + (size_t)(s0 + row) * HDIM + kt + q * 8;
        asm volatile("cp.async.cg.shared.global [%0], [%1], 16;"
                     :: "r"(dst), "l"(src) : "memory");
    }
    #pragma unroll
    for (int j = 0; j < 2; j++) {              // B: 512 x 16B
        int idx = tid + j * 256;
        int row = idx >> 2, q = idx & 3;
        unsigned dst = bb + (unsigned)(row * 80 + q * 16);
        const __nv_bfloat16* src = g_wb + (size_t)(i0 + row) * HDIM + kt + q * 8;
        asm volatile("cp.async.cg.shared.global [%0], [%1], 16;"
                     :: "r"(dst), "l"(src) : "memory");
    }
    asm volatile("cp.async.commit_group;" ::: "memory");
}

// ---------------------------------------------------------------------------
// Convert kernels (fp32 -> bf16, RTN)
// ---------------------------------------------------------------------------
__global__ void convert_enc_kernel(const float* __restrict__ enc) {
    size_t gid = (size_t)blockIdx.x * blockDim.x + threadIdx.x;   // 4194304
    size_t base = gid * 8;
    float4 a = *(const float4*)(enc + base);
    float4 b = *(const float4*)(enc + base + 4);
    __nv_bfloat162 r[4];
    r[0] = __floats2bfloat162_rn(a.x, a.y);
    r[1] = __floats2bfloat162_rn(a.z, a.w);
    r[2] = __floats2bfloat162_rn(b.x, b.y);
    r[3] = __floats2bfloat162_rn(b.z, b.w);
    *(uint4*)(g_encb + base) = *(uint4*)r;
}
__global__ void convert_w_kernel(const float* __restrict__ attn_w) {
    size_t gid = (size_t)blockIdx.x * blockDim.x + threadIdx.x;   // 131072
    size_t base = gid * 8;
    size_t i = base >> 10, k = base & 1023;
    const float* src = attn_w + i * H3 + 2 * HDIM + k;
    float4 a = *(const float4*)src;
    float4 b = *(const float4*)(src + 4);
    __nv_bfloat162 r[4];
    r[0] = __floats2bfloat162_rn(a.x, a.y);
    r[1] = __floats2bfloat162_rn(a.z, a.w);
    r[2] = __floats2bfloat162_rn(b.x, b.y);
    r[3] = __floats2bfloat162_rn(b.z, b.w);
    *(uint4*)(g_wb + base) = *(uint4*)r;
}

// ---------------------------------------------------------------------------
// Kernel 1: c[i] = hidden . attn_w[i, 0:2H] + attn_b[i]   (fp32)
// ---------------------------------------------------------------------------
__global__ void precompute_c_kernel(const float* __restrict__ hidden,
                                    const float* __restrict__ attn_w,
                                    const float* __restrict__ attn_b) {
    int warp = (blockIdx.x * blockDim.x + threadIdx.x) >> 5;
    int lane = threadIdx.x & 31;
    if (warp >= HDIM) return;
    const float* wrow = attn_w + (size_t)warp * H3;
    float s = 0.f;
    #pragma unroll 8
    for (int j = lane; j < 2 * HDIM; j += 32)
        s += hidden[j] * wrow[j];
    #pragma unroll
    for (int off = 16; off; off >>= 1)
        s += __shfl_down_sync(0xffffffffu, s, off);
    if (lane == 0) g_c[warp] = s + attn_b[warp];
}

// ---------------------------------------------------------------------------
// Kernel 2: bf16 mma.sync m16n8k16 GEMM + fused tanh / v-dot / exp epilogue.
//   8 warps = 4(M) x 2(N).  Warp tile 32x64.  mt=2, nt=8.  acc = 64 regs.
// ---------------------------------------------------------------------------
__global__ __launch_bounds__(256, 2)
void attn_main_kernel(const float* __restrict__ v_w, float* __restrict__ out) {
    extern __shared__ char smem[];
    const unsigned sb = smem_u32(smem);
    const int tid  = threadIdx.x;
    const int wid  = tid >> 5;
    const int lane = tid & 31;
    const int g    = lane >> 2;        // 0..7
    const int c    = lane & 3;         // 0..3
    const int m0   = (wid & 3) * 32;   // 4 M-warps
    const int n0   = (wid >> 2) * 64;  // 2 N-warps
    const int s0   = blockIdx.x * BM;

    float* sc  = (float*)(smem + SM_C);
    float* sv  = (float*)(smem + SM_V);
    float* red = (float*)(smem + SM_RED);
    float* sr  = (float*)(smem + SM_SR);

    for (int i = tid; i < HDIM; i += 256) { sc[i] = g_c[i]; sv[i] = v_w[i]; }

    // ldmatrix lane offsets, 80 B row stride
    // A x4 (per mt,ks): mats {r0-7,k0-7},{r8-15,k0-7},{r0-7,k8-15},{r8-15,k8-15}
    const unsigned aLane =
        (unsigned)((m0 + ((lane >> 3) & 1) * 8 + (lane & 7)) * 80
                   + (lane >> 4) * 16);
    // B x4 (per p,ks): mats {n0-7,k0-7},{n0-7,k8-15},{n8-15,k0-7},{n8-15,k8-15}
    const unsigned bLane =
        (unsigned)((n0 + (lane >> 4) * 8 + (lane & 7)) * 80
                   + ((lane >> 3) & 1) * 16);

    load_chunk(sb, 0, 0, s0, tid);
    load_chunk(sb, 1, 1, s0, tid);

    float acc[2][8][4];
    float part[4] = {0.f, 0.f, 0.f, 0.f};

    for (int gc = 0; gc < NCHUNKS; gc++) {
        const int stage = gc % NSTAGE;
        if (gc < NCHUNKS - 1)
            asm volatile("cp.async.wait_group 1;" ::: "memory");
        else
            asm volatile("cp.async.wait_group 0;" ::: "memory");
        __syncthreads();

        if (gc + 2 < NCHUNKS)
            load_chunk(sb, (gc + 2) % NSTAGE, gc + 2, s0, tid);

        if ((gc & 31) == 0) {
            #pragma unroll
            for (int mt = 0; mt < 2; mt++)
                #pragma unroll
                for (int nt = 0; nt < 8; nt++)
                    #pragma unroll
                    for (int q = 0; q < 4; q++) acc[mt][nt][q] = 0.f;
        }

        const unsigned aB = sb + SM_A + stage * A_STG + aLane;
        const unsigned bB = sb + SM_B + stage * B_STG + bLane;

        #pragma unroll
        for (int ks = 0; ks < 2; ks++) {       // two k16 steps cover KCH=32
            uint32_t af[2][4], bf[4][4];
            #pragma unroll
            for (int mt = 0; mt < 2; mt++)
                ldsm4(af[mt], aB + mt * (16 * 80) + ks * 32);
            #pragma unroll
            for (int p = 0; p < 4; p++)
                ldsm4(bf[p], bB + p * (16 * 80) + ks * 32);
            #pragma unroll
            for (int p = 0; p < 4; p++) {
                #pragma unroll
                for (int mt = 0; mt < 2; mt++) {
                    mma16(acc[mt][2 * p + 0], af[mt], bf[p][0], bf[p][1]);
                    mma16(acc[mt][2 * p + 1], af[mt], bf[p][2], bf[p][3]);
                }
            }
        }

        // per-pass fused epilogue: tanh + v-dot into register partials
        if ((gc & 31) == 31) {
            const int pass = gc >> 5;
            #pragma unroll
            for (int mt = 0; mt < 2; mt++) {
                #pragma unroll
                for (int nt = 0; nt < 8; nt++) {
                    int i = pass * BN + n0 + nt * 8 + c * 2;
                    float v0 = sv[i],     c0 = sc[i];
                    float v1 = sv[i + 1], c1 = sc[i + 1];
                    part[mt*2+0] = fmaf(v0, fast_tanh(acc[mt][nt][0] + c0),
                                   fmaf(v1, fast_tanh(acc[mt][nt][1] + c1),
                                        part[mt*2+0]));
                    part[mt*2+1] = fmaf(v0, fast_tanh(acc[mt][nt][2] + c0),
                                   fmaf(v1, fast_tanh(acc[mt][nt][3] + c1),
                                        part[mt*2+1]));
                }
            }
        }
    }

    // reduce the 4 quad lanes (same rows, different col pairs)
    #pragma unroll
    for (int r = 0; r < 4; r++) {
        part[r] += __shfl_xor_sync(0xffffffffu, part[r], 1);
        part[r] += __shfl_xor_sync(0xffffffffu, part[r], 2);
    }
    if (c == 0) {
        const int nw = wid >> 2;
        #pragma unroll
        for (int mt = 0; mt < 2; mt++) {
            #pragma unroll
            for (int h = 0; h < 2; h++) {
                int row = m0 + mt * 16 + h * 8 + g;
                red[nw * 128 + row] = part[mt * 2 + h];
            }
        }
    }
    __syncthreads();

    float ex = 0.f;
    if (tid < BM) {
        float logit = red[tid] + red[128 + tid];  // |logit| <= ~26
        ex = expf(logit);
        out[s0 + tid] = ex;
    }
    #pragma unroll
    for (int off = 16; off; off >>= 1)
        ex += __shfl_down_sync(0xffffffffu, ex, off);
    if (lane == 0 && wid < 4) sr[wid] = ex;
    __syncthreads();
    if (tid == 0)
        g_part[blockIdx.x] = sr[0] + sr[1] + sr[2] + sr[3];
}

// ---------------------------------------------------------------------------
// Kernel 3: deterministic reduction -> g_inv
// ---------------------------------------------------------------------------
__global__ void reduce_total_kernel() {
    __shared__ float sm[GRID_MAIN];
    int t = threadIdx.x;
    sm[t] = g_part[t];
    __syncthreads();
    #pragma unroll
    for (int o = GRID_MAIN / 2; o > 0; o >>= 1) {
        if (t < o) sm[t] += sm[t + o];
        __syncthreads();
    }
    if (t == 0) g_inv = 1.f / sm[0];
}

// ---------------------------------------------------------------------------
// Kernel 4: normalize
// ---------------------------------------------------------------------------
__global__ void normalize_kernel(float* __restrict__ out) {
    int i = blockIdx.x * blockDim.x + threadIdx.x;
    if (i < S_LEN) out[i] *= g_inv;
}

// ---------------------------------------------------------------------------
extern "C" void kernel_launch(void* const* d_in, const int* in_sizes, int n_in,
                              void* d_out, int out_size) {
    const float* hidden = (const float*)d_in[0];
    const float* enc    = (const float*)d_in[1];
    const float* attn_w = (const float*)d_in[2];
    const float* attn_b = (const float*)d_in[3];
    const float* v_w    = (const float*)d_in[4];
    float* out = (float*)d_out;

    cudaFuncSetAttribute(attn_main_kernel,
                         cudaFuncAttributeMaxDynamicSharedMemorySize, SMEM_TOTAL);

    convert_enc_kernel<<<16384, 256>>>(enc);
    convert_w_kernel<<<512, 256>>>(attn_w);
    precompute_c_kernel<<<128, 256>>>(hidden, attn_w, attn_b);
    attn_main_kernel<<<GRID_MAIN, 256, SMEM_TOTAL>>>(v_w, out);
    reduce_total_kernel<<<1, GRID_MAIN>>>();
    normalize_kernel<<<S_LEN / 256, 256>>>(out);
}

// round 8
// speedup vs baseline: 7.3519x; 1.2374x over previous
#include <cuda_runtime.h>
#include <cuda_bf16.h>
#include <cstdint>

#define S_LEN 32768
#define HDIM  1024
#define H3    3072
#define BM    128
#define BN    128                  // i-cols per pass
#define NPASS 8
#define KCH   64                   // k elements per chunk (128 B bf16 row)
#define CH_PER_PASS (HDIM / KCH)   // 16
#define NCHUNKS (NPASS * CH_PER_PASS)    // 128
#define GRID_MAIN (S_LEN / BM)     // 256
#define NSTAGE 3

// SMEM (bytes). Rows are exactly 128 B, XOR-swizzled (SW128) -> no padding.
#define STG    16384               // 128 rows * 128 B
#define SM_A   0
#define SM_B   (NSTAGE * STG)                // 49152
#define SM_C   (SM_B + NSTAGE * STG)         // 98304
#define SM_V   (SM_C + 4096)                 // 102400
#define SM_RED (SM_V + 4096)                 // 106496 (256 floats)
#define SM_SR  (SM_RED + 1024)               // 107520
#define SMEM_TOTAL (SM_SR + 16)              // 107536 (x2 CTA/SM = 215 KB)

__device__ float g_c[HDIM];
__device__ float g_part[GRID_MAIN];
__device__ float g_inv;
__device__ __align__(16) __nv_bfloat16 g_encb[(size_t)S_LEN * HDIM]; // 64 MB
__device__ __align__(16) __nv_bfloat16 g_wb[HDIM * HDIM];            // 2 MB

// ---------------- helpers ----------------
__device__ __forceinline__ unsigned smem_u32(const void* p) {
    return (unsigned)__cvta_generic_to_shared(p);
}
__device__ __forceinline__ float fast_tanh(float x) {
    float e, r;
    asm("ex2.approx.f32 %0, %1;" : "=f"(e) : "f"(x * 2.885390082f));
    asm("rcp.approx.f32 %0, %1;" : "=f"(r) : "f"(e + 1.0f));
    return fmaf(-2.0f, r, 1.0f);
}
__device__ __forceinline__ void mma16(float* d, const uint32_t* a,
                                      uint32_t b0, uint32_t b1) {
    asm volatile(
        "mma.sync.aligned.m16n8k16.row.col.f32.bf16.bf16.f32 "
        "{%0,%1,%2,%3}, {%4,%5,%6,%7}, {%8,%9}, {%0,%1,%2,%3};"
        : "+f"(d[0]), "+f"(d[1]), "+f"(d[2]), "+f"(d[3])
        : "r"(a[0]), "r"(a[1]), "r"(a[2]), "r"(a[3]), "r"(b0), "r"(b1));
}
__device__ __forceinline__ void ldsm4(uint32_t* d, unsigned addr) {
    asm volatile(
        "ldmatrix.sync.aligned.m8n8.x4.shared.b16 {%0,%1,%2,%3}, [%4];"
        : "=r"(d[0]), "=r"(d[1]), "=r"(d[2]), "=r"(d[3]) : "r"(addr));
}

// cp.async one chunk: A 128x64 bf16, B 128x64 bf16, SW128 XOR swizzle
__device__ __forceinline__ void load_chunk(unsigned sb, int stage, int gc,
                                           int s0, int tid) {
    const int kt = (gc & (CH_PER_PASS - 1)) * KCH;
    const int i0 = (gc / CH_PER_PASS) * BN;
    const unsigned ab = sb + SM_A + stage * STG;
    const unsigned bb = sb + SM_B + stage * STG;
    #pragma unroll
    for (int j = 0; j < 4; j++) {              // A: 1024 x 16B
        int idx = tid + j * 256;
        int row = idx >> 3, q = idx & 7;
        unsigned dst = ab + (unsigned)(row * 128 + ((q ^ (row & 7)) * 16));
        const __nv_bfloat16* src = g_encb + (size_t)(s0 + row) * HDIM + kt + q * 8;
        asm volatile("cp.async.cg.shared.global [%0], [%1], 16;"
                     :: "r"(dst), "l"(src) : "memory");
    }
    #pragma unroll
    for (int j = 0; j < 4; j++) {              // B: 1024 x 16B
        int idx = tid + j * 256;
        int row = idx >> 3, q = idx & 7;
        unsigned dst = bb + (unsigned)(row * 128 + ((q ^ (row & 7)) * 16));
        const __nv_bfloat16* src = g_wb + (size_t)(i0 + row) * HDIM + kt + q * 8;
        asm volatile("cp.async.cg.shared.global [%0], [%1], 16;"
                     :: "r"(dst), "l"(src) : "memory");
    }
    asm volatile("cp.async.commit_group;" ::: "memory");
}

// ---------------------------------------------------------------------------
// Convert kernels (fp32 -> bf16, RTN)
// ---------------------------------------------------------------------------
__global__ void convert_enc_kernel(const float* __restrict__ enc) {
    size_t gid = (size_t)blockIdx.x * blockDim.x + threadIdx.x;
    size_t base = gid * 8;
    float4 a = *(const float4*)(enc + base);
    float4 b = *(const float4*)(enc + base + 4);
    __nv_bfloat162 r[4];
    r[0] = __floats2bfloat162_rn(a.x, a.y);
    r[1] = __floats2bfloat162_rn(a.z, a.w);
    r[2] = __floats2bfloat162_rn(b.x, b.y);
    r[3] = __floats2bfloat162_rn(b.z, b.w);
    *(uint4*)(g_encb + base) = *(uint4*)r;
}
__global__ void convert_w_kernel(const float* __restrict__ attn_w) {
    size_t gid = (size_t)blockIdx.x * blockDim.x + threadIdx.x;
    size_t base = gid * 8;
    size_t i = base >> 10, k = base & 1023;
    const float* src = attn_w + i * H3 + 2 * HDIM + k;
    float4 a = *(const float4*)src;
    float4 b = *(const float4*)(src + 4);
    __nv_bfloat162 r[4];
    r[0] = __floats2bfloat162_rn(a.x, a.y);
    r[1] = __floats2bfloat162_rn(a.z, a.w);
    r[2] = __floats2bfloat162_rn(b.x, b.y);
    r[3] = __floats2bfloat162_rn(b.z, b.w);
    *(uint4*)(g_wb + base) = *(uint4*)r;
}

// ---------------------------------------------------------------------------
// Kernel 1: c[i] = hidden . attn_w[i, 0:2H] + attn_b[i]   (fp32)
// ---------------------------------------------------------------------------
__global__ void precompute_c_kernel(const float* __restrict__ hidden,
                                    const float* __restrict__ attn_w,
                                    const float* __restrict__ attn_b) {
    int warp = (blockIdx.x * blockDim.x + threadIdx.x) >> 5;
    int lane = threadIdx.x & 31;
    if (warp >= HDIM) return;
    const float* wrow = attn_w + (size_t)warp * H3;
    float s = 0.f;
    #pragma unroll 8
    for (int j = lane; j < 2 * HDIM; j += 32)
        s += hidden[j] * wrow[j];
    #pragma unroll
    for (int off = 16; off; off >>= 1)
        s += __shfl_down_sync(0xffffffffu, s, off);
    if (lane == 0) g_c[warp] = s + attn_b[warp];
}

// ---------------------------------------------------------------------------
// Kernel 2: bf16 m16n8k16 GEMM + fused tanh / v-dot / exp epilogue.
//   8 warps = 4(M) x 2(N).  Warp tile 32x64.  mt=2, nt=8.  acc = 64 regs.
//   KCH=64: 64 MMAs + 24 LDSM per warp between consecutive barriers.
// ---------------------------------------------------------------------------
__global__ __launch_bounds__(256, 2)
void attn_main_kernel(const float* __restrict__ v_w, float* __restrict__ out) {
    extern __shared__ char smem[];
    const unsigned sb = smem_u32(smem);
    const int tid  = threadIdx.x;
    const int wid  = tid >> 5;
    const int lane = tid & 31;
    const int g    = lane >> 2;        // 0..7
    const int c    = lane & 3;         // 0..3
    const int m0   = (wid & 3) * 32;   // 4 M-warps
    const int n0   = (wid >> 2) * 64;  // 2 N-warps
    const int s0   = blockIdx.x * BM;

    float* sc  = (float*)(smem + SM_C);
    float* sv  = (float*)(smem + SM_V);
    float* red = (float*)(smem + SM_RED);
    float* sr  = (float*)(smem + SM_SR);

    for (int i = tid; i < HDIM; i += 256) { sc[i] = g_c[i]; sv[i] = v_w[i]; }

    // ldmatrix lane geometry (rows fixed per lane; column 16B unit XOR-swizzled)
    const int arow  = m0 + ((lane >> 3) & 1) * 8 + (lane & 7); // + mt*16
    const int aswz  = arow & 7;
    const int acol  = lane >> 4;                               // 0..1 (k half)
    const int brow  = n0 + (lane >> 4) * 8 + (lane & 7);       // + p*16
    const int bswz  = brow & 7;
    const int bcol  = (lane >> 3) & 1;                         // 0..1 (k half)

    load_chunk(sb, 0, 0, s0, tid);
    load_chunk(sb, 1, 1, s0, tid);

    float acc[2][8][4];
    float part[4] = {0.f, 0.f, 0.f, 0.f};

    for (int gc = 0; gc < NCHUNKS; gc++) {
        const int stage = gc % NSTAGE;
        if (gc < NCHUNKS - 1)
            asm volatile("cp.async.wait_group 1;" ::: "memory");
        else
            asm volatile("cp.async.wait_group 0;" ::: "memory");
        __syncthreads();

        if (gc + 2 < NCHUNKS)
            load_chunk(sb, (gc + 2) % NSTAGE, gc + 2, s0, tid);

        if ((gc & (CH_PER_PASS - 1)) == 0) {
            #pragma unroll
            for (int mt = 0; mt < 2; mt++)
                #pragma unroll
                for (int nt = 0; nt < 8; nt++)
                    #pragma unroll
                    for (int q = 0; q < 4; q++) acc[mt][nt][q] = 0.f;
        }

        const unsigned aS = sb + SM_A + stage * STG;
        const unsigned bS = sb + SM_B + stage * STG;

        #pragma unroll
        for (int ks = 0; ks < 4; ks++) {       // four k16 steps cover KCH=64
            uint32_t af[2][4], bf[4][4];
            const int aq = ((ks * 2 + acol) ^ aswz) * 16;
            const int bq = ((ks * 2 + bcol) ^ bswz) * 16;
            #pragma unroll
            for (int mt = 0; mt < 2; mt++)
                ldsm4(af[mt], aS + (unsigned)((arow + mt * 16) * 128 + aq));
            #pragma unroll
            for (int p = 0; p < 4; p++)
                ldsm4(bf[p], bS + (unsigned)((brow + p * 16) * 128 + bq));
            #pragma unroll
            for (int p = 0; p < 4; p++) {
                #pragma unroll
                for (int mt = 0; mt < 2; mt++) {
                    mma16(acc[mt][2 * p + 0], af[mt], bf[p][0], bf[p][1]);
                    mma16(acc[mt][2 * p + 1], af[mt], bf[p][2], bf[p][3]);
                }
            }
        }

        // per-pass fused epilogue: tanh + v-dot into register partials
        if ((gc & (CH_PER_PASS - 1)) == CH_PER_PASS - 1) {
            const int pass = gc / CH_PER_PASS;
            #pragma unroll
            for (int mt = 0; mt < 2; mt++) {
                #pragma unroll
                for (int nt = 0; nt < 8; nt++) {
                    int i = pass * BN + n0 + nt * 8 + c * 2;
                    float v0 = sv[i],     c0 = sc[i];
                    float v1 = sv[i + 1], c1 = sc[i + 1];
                    part[mt*2+0] = fmaf(v0, fast_tanh(acc[mt][nt][0] + c0),
                                   fmaf(v1, fast_tanh(acc[mt][nt][1] + c1),
                                        part[mt*2+0]));
                    part[mt*2+1] = fmaf(v0, fast_tanh(acc[mt][nt][2] + c0),
                                   fmaf(v1, fast_tanh(acc[mt][nt][3] + c1),
                                        part[mt*2+1]));
                }
            }
        }
    }

    // reduce the 4 quad lanes (same rows, different col pairs)
    #pragma unroll
    for (int r = 0; r < 4; r++) {
        part[r] += __shfl_xor_sync(0xffffffffu, part[r], 1);
        part[r] += __shfl_xor_sync(0xffffffffu, part[r], 2);
    }
    if (c == 0) {
        const int nw = wid >> 2;
        #pragma unroll
        for (int mt = 0; mt < 2; mt++) {
            #pragma unroll
            for (int h = 0; h < 2; h++) {
                int row = m0 + mt * 16 + h * 8 + g;
                red[nw * 128 + row] = part[mt * 2 + h];
            }
        }
    }
    __syncthreads();

    float ex = 0.f;
    if (tid < BM) {
        float logit = red[tid] + red[128 + tid];  // |logit| <= ~26
        ex = expf(logit);
        out[s0 + tid] = ex;
    }
    #pragma unroll
    for (int off = 16; off; off >>= 1)
        ex += __shfl_down_sync(0xffffffffu, ex, off);
    if (lane == 0 && wid < 4) sr[wid] = ex;
    __syncthreads();
    if (tid == 0)
        g_part[blockIdx.x] = sr[0] + sr[1] + sr[2] + sr[3];
}

// ---------------------------------------------------------------------------
// Kernel 3: deterministic reduction -> g_inv
// ---------------------------------------------------------------------------
__global__ void reduce_total_kernel() {
    __shared__ float sm[GRID_MAIN];
    int t = threadIdx.x;
    sm[t] = g_part[t];
    __syncthreads();
    #pragma unroll
    for (int o = GRID_MAIN / 2; o > 0; o >>= 1) {
        if (t < o) sm[t] += sm[t + o];
        __syncthreads();
    }
    if (t == 0) g_inv = 1.f / sm[0];
}

// ---------------------------------------------------------------------------
// Kernel 4: normalize
// ---------------------------------------------------------------------------
__global__ void normalize_kernel(float* __restrict__ out) {
    int i = blockIdx.x * blockDim.x + threadIdx.x;
    if (i < S_LEN) out[i] *= g_inv;
}

// ---------------------------------------------------------------------------
extern "C" void kernel_launch(void* const* d_in, const int* in_sizes, int n_in,
                              void* d_out, int out_size) {
    const float* hidden = (const float*)d_in[0];
    const float* enc    = (const float*)d_in[1];
    const float* attn_w = (const float*)d_in[2];
    const float* attn_b = (const float*)d_in[3];
    const float* v_w    = (const float*)d_in[4];
    float* out = (float*)d_out;

    cudaFuncSetAttribute(attn_main_kernel,
                         cudaFuncAttributeMaxDynamicSharedMemorySize, SMEM_TOTAL);

    convert_enc_kernel<<<16384, 256>>>(enc);
    convert_w_kernel<<<512, 256>>>(attn_w);
    precompute_c_kernel<<<128, 256>>>(hidden, attn_w, attn_b);
    attn_main_kernel<<<GRID_MAIN, 256, SMEM_TOTAL>>>(v_w, out);
    reduce_total_kernel<<<1, GRID_MAIN>>>();
    normalize_kernel<<<S_LEN / 256, 256>>>(out);
}